// round 4
// baseline (speedup 1.0000x reference)
#include <cuda_runtime.h>
#include <cuda_bf16.h>
#include <stdint.h>

#define D 128
#define E_CAP 16384
#define N_CAP 65536
#define NNZ_CAP (1 << 20)
#define EPS 1e-8f
#define CHUNK 4096
#define NBLK_E (E_CAP / CHUNK)            // 4
#define NBLK_N (N_CAP / CHUNK)            // 16
#define NBLK_SCAN (NBLK_E + NBLK_N)       // 20

// ---------------- scratch (static device globals; no allocation) ------------
__device__ float    g_xnode[(size_t)N_CAP * D];      // fp32 (exact residual)
__device__ unsigned g_xnode_h[(size_t)N_CAP * 64];   // bf16x2 gather mirror
__device__ unsigned g_heattr_h[(size_t)E_CAP * 64];  // bf16x2 hyperedge attr
__device__ int g_eidx[NNZ_CAP];
__device__ int g_nidx[NNZ_CAP];
__device__ int g_eoff[E_CAP + 1];
__device__ int g_noff[N_CAP + 1];
__device__ int g_cnts[E_CAP + N_CAP];                // counts, then reused as cursors
__device__ int g_bsum[NBLK_SCAN];
__device__ int g_is64;

#define ECNT (g_cnts)
#define NCNT (g_cnts + E_CAP)

// ---------------- zero counters + index dtype detect -------------------------
__global__ void zero_cnts_kernel(const int* __restrict__ h) {
    int i = blockIdx.x * blockDim.x + threadIdx.x;
    ((int4*)g_cnts)[i] = make_int4(0, 0, 0, 0);
    if (i == 0)
        g_is64 = (h[1] == 0 && h[3] == 0 && h[5] == 0 && h[7] == 0) ? 1 : 0;
}

// ---------------- CSR build: histogram (4 entries / thread) ------------------
__global__ __launch_bounds__(256) void hist_kernel(const void* __restrict__ base, int nnz) {
    int i0 = (blockIdx.x * blockDim.x + threadIdx.x) * 4;
    if (i0 >= nnz) return;
    int m = nnz - i0; if (m > 4) m = 4;
    int src[4], e[4];
    if (g_is64) {
        const long long* p = (const long long*)base;
        #pragma unroll
        for (int k = 0; k < 4; k++) {
            int i = i0 + ((k < m) ? k : 0);
            src[k] = (int)__ldg(p + i);
            e[k]   = (int)__ldg(p + nnz + i);
        }
    } else {
        const int* p = (const int*)base;
        #pragma unroll
        for (int k = 0; k < 4; k++) {
            int i = i0 + ((k < m) ? k : 0);
            src[k] = __ldg(p + i);
            e[k]   = __ldg(p + nnz + i);
        }
    }
    #pragma unroll
    for (int k = 0; k < 4; k++) {
        if (k < m) {
            atomicAdd(&ECNT[e[k]], 1);
            atomicAdd(&NCNT[src[k]], 1);
        }
    }
}

// ---------------- CSR build: 2-level exclusive scan --------------------------
__global__ __launch_bounds__(1024) void scan_local_kernel() {
    int b = blockIdx.x;
    const int* cnt; int* off; int lo;
    if (b < NBLK_E) { cnt = ECNT; off = g_eoff; lo = b * CHUNK; }
    else            { cnt = NCNT; off = g_noff; lo = (b - NBLK_E) * CHUNK; }

    __shared__ int wsum[32];
    int tid = threadIdx.x, lane = tid & 31, wid = tid >> 5;
    int idx = lo + tid * 4;

    int4 v = *(const int4*)(cnt + idx);
    int tsum = v.x + v.y + v.z + v.w;
    int incl = tsum;
    #pragma unroll
    for (int s = 1; s < 32; s <<= 1) {
        int t = __shfl_up_sync(0xffffffffu, incl, s);
        if (lane >= s) incl += t;
    }
    if (lane == 31) wsum[wid] = incl;
    __syncthreads();
    if (wid == 0) {
        int w = wsum[lane];
        int wi = w;
        #pragma unroll
        for (int s = 1; s < 32; s <<= 1) {
            int t = __shfl_up_sync(0xffffffffu, wi, s);
            if (lane >= s) wi += t;
        }
        wsum[lane] = wi - w;
    }
    __syncthreads();
    int ex = wsum[wid] + incl - tsum;
    off[idx]     = ex;
    off[idx + 1] = ex + v.x;
    off[idx + 2] = ex + v.x + v.y;
    off[idx + 3] = ex + v.x + v.y + v.z;
    if (tid == 1023) g_bsum[b] = ex + tsum;
}

// fixup adds cross-block base AND initializes cursors (= start offsets)
__global__ __launch_bounds__(1024) void scan_fixup_kernel() {
    int b = blockIdx.x;
    __shared__ int s_base;
    int tid = threadIdx.x;
    if (tid == 0) {
        int start = (b < NBLK_E) ? 0 : NBLK_E;
        int base = 0;
        for (int i = start; i < b; i++) base += g_bsum[i];
        s_base = base;
    }
    __syncthreads();
    int base = s_base;
    int* off; int* cur; int lo;
    if (b < NBLK_E) { off = g_eoff; cur = ECNT; lo = b * CHUNK; }
    else            { off = g_noff; cur = NCNT; lo = (b - NBLK_E) * CHUNK; }
    int idx = lo + tid * 4;
    int4 o = *(int4*)(off + idx);
    o.x += base; o.y += base; o.z += base; o.w += base;
    *(int4*)(off + idx) = o;
    *(int4*)(cur + idx) = o;   // cursors start at segment start
    if (tid == 0) {
        if (b == NBLK_E - 1)    g_eoff[E_CAP] = base + g_bsum[b];
        if (b == NBLK_SCAN - 1) g_noff[N_CAP] = base + g_bsum[b];
    }
}

// ---------------- CSR build: bucket fill (cursor atomics, 4/thread) ----------
__global__ __launch_bounds__(256) void fill_kernel(const void* __restrict__ base, int nnz) {
    int i0 = (blockIdx.x * blockDim.x + threadIdx.x) * 4;
    if (i0 >= nnz) return;
    int m = nnz - i0; if (m > 4) m = 4;
    int src[4], e[4];
    if (g_is64) {
        const long long* p = (const long long*)base;
        #pragma unroll
        for (int k = 0; k < 4; k++) {
            int i = i0 + ((k < m) ? k : 0);
            src[k] = (int)__ldg(p + i);
            e[k]   = (int)__ldg(p + nnz + i);
        }
    } else {
        const int* p = (const int*)base;
        #pragma unroll
        for (int k = 0; k < 4; k++) {
            int i = i0 + ((k < m) ? k : 0);
            src[k] = __ldg(p + i);
            e[k]   = __ldg(p + nnz + i);
        }
    }
    int pe[4], pn[4];
    #pragma unroll
    for (int k = 0; k < 4; k++) {
        if (k < m) {
            pe[k] = atomicAdd(&ECNT[e[k]], 1);
            pn[k] = atomicAdd(&NCNT[src[k]], 1);
        }
    }
    #pragma unroll
    for (int k = 0; k < 4; k++) {
        if (k < m) {
            g_eidx[pe[k]] = src[k];
            g_nidx[pn[k]] = e[k];
        }
    }
}

// ---------------- GEMM: g_xnode = x @ W^T (packed f32x2 FMA) -----------------
#define WT_STRIDE 132
#define GEMM_SMEM ((128 * WT_STRIDE + 64 * WT_STRIDE) * 4)

__device__ __forceinline__ unsigned long long fma2(unsigned long long a,
                                                   unsigned long long b,
                                                   unsigned long long c) {
    unsigned long long d;
    asm("fma.rn.f32x2 %0, %1, %2, %3;" : "=l"(d) : "l"(a), "l"(b), "l"(c));
    return d;
}

__global__ __launch_bounds__(256) void gemm_kernel(const float* __restrict__ x,
                                                   const float* __restrict__ W,
                                                   int N) {
    extern __shared__ float sm[];
    float* WT = sm;                       // [128][132], WT[k][j] = W[j][k]
    float* Xs = sm + 128 * WT_STRIDE;     // [64][132]

    int t = threadIdx.x;
    int row0 = blockIdx.x * 64;

    #pragma unroll
    for (int i = 0; i < 64; i++) {
        int idx = t + i * 256;
        int j = idx >> 7, k = idx & 127;
        WT[k * WT_STRIDE + j] = W[idx];
    }
    #pragma unroll
    for (int i = 0; i < 32; i++) {
        int idx = t + i * 256;
        int r = idx >> 7, k = idx & 127;
        int row = row0 + r;
        if (row >= N) row = N - 1;
        Xs[r * WT_STRIDE + k] = x[(size_t)row * D + k];
    }
    __syncthreads();

    int tx = t & 15, ty = t >> 4;
    int c0 = tx * 8, r0 = ty * 4;

    unsigned long long acc[4][4];
    #pragma unroll
    for (int i = 0; i < 4; i++)
        #pragma unroll
        for (int j = 0; j < 4; j++) acc[i][j] = 0ull;

    #pragma unroll 4
    for (int k = 0; k < 128; k++) {
        ulonglong2 wa = *(const ulonglong2*)(WT + k * WT_STRIDE + c0);
        ulonglong2 wb = *(const ulonglong2*)(WT + k * WT_STRIDE + c0 + 4);
        #pragma unroll
        for (int i = 0; i < 4; i++) {
            unsigned au = __float_as_uint(Xs[(r0 + i) * WT_STRIDE + k]);
            unsigned long long aa;
            asm("mov.b64 %0, {%1, %1};" : "=l"(aa) : "r"(au));
            acc[i][0] = fma2(aa, wa.x, acc[i][0]);
            acc[i][1] = fma2(aa, wa.y, acc[i][1]);
            acc[i][2] = fma2(aa, wb.x, acc[i][2]);
            acc[i][3] = fma2(aa, wb.y, acc[i][3]);
        }
    }

    #pragma unroll
    for (int i = 0; i < 4; i++) {
        int row = row0 + r0 + i;
        if (row < N) {
            ulonglong2 o0; o0.x = acc[i][0]; o0.y = acc[i][1];
            ulonglong2 o1; o1.x = acc[i][2]; o1.y = acc[i][3];
            *(ulonglong2*)(g_xnode + (size_t)row * D + c0)     = o0;
            *(ulonglong2*)(g_xnode + (size_t)row * D + c0 + 4) = o1;
            uint4 h;
            #pragma unroll
            for (int j = 0; j < 4; j++) {
                unsigned lo, hi;
                asm("mov.b64 {%0, %1}, %2;" : "=r"(lo), "=r"(hi) : "l"(acc[i][j]));
                unsigned r2;
                asm("cvt.rn.bf16x2.f32 %0, %1, %2;" : "=r"(r2)
                    : "f"(__uint_as_float(hi)), "f"(__uint_as_float(lo)));
                ((unsigned*)&h)[j] = r2;
            }
            *(uint4*)(g_xnode_h + (size_t)row * 64 + tx * 4) = h;
        }
    }
}

// ---------------- phase A: per-edge pull reduction (bf16 gather, unroll 4) ---
__global__ __launch_bounds__(128) void edge_agg_kernel() {
    int half = threadIdx.x >> 6;
    int t = threadIdx.x & 63;
    int e = blockIdx.x * 2 + half;
    int beg = g_eoff[e], end = g_eoff[e + 1];
    if (beg == end) return;

    float s0[4] = {0.f, 0.f, 0.f, 0.f};
    float s1[4] = {0.f, 0.f, 0.f, 0.f};
    int j = beg;
    for (; j + 4 <= end; j += 4) {
        #pragma unroll
        for (int k = 0; k < 4; k++) {
            unsigned u = g_xnode_h[(size_t)g_eidx[j + k] * 64 + t];
            s0[k] += __uint_as_float(u << 16);
            s1[k] += __uint_as_float(u & 0xffff0000u);
        }
    }
    for (; j < end; j++) {
        unsigned u = g_xnode_h[(size_t)g_eidx[j] * 64 + t];
        s0[0] += __uint_as_float(u << 16);
        s1[0] += __uint_as_float(u & 0xffff0000u);
    }
    float inv = 1.0f / ((float)(end - beg) + EPS);
    float f0 = ((s0[0] + s0[1]) + (s0[2] + s0[3])) * inv;
    float f1 = ((s1[0] + s1[1]) + (s1[2] + s1[3])) * inv;
    unsigned r;
    asm("cvt.rn.bf16x2.f32 %0, %1, %2;" : "=r"(r) : "f"(f1), "f"(f0));
    g_heattr_h[(size_t)e * 64 + t] = r;
}

// ---------------- phase B: per-node pull + fused finalize (unroll 4) ---------
__global__ __launch_bounds__(256) void node_agg_kernel(const float* __restrict__ bias,
                                                       float* __restrict__ out,
                                                       int N) {
    int w = (blockIdx.x * blockDim.x + threadIdx.x) >> 5;
    if (w >= N) return;
    int lane = threadIdx.x & 31;
    int beg = g_noff[w], end = g_noff[w + 1];

    float4 acc[4];
    #pragma unroll
    for (int k = 0; k < 4; k++) acc[k] = make_float4(0.f, 0.f, 0.f, 0.f);

    int j = beg;
    for (; j + 4 <= end; j += 4) {
        #pragma unroll
        for (int k = 0; k < 4; k++) {
            uint2 u = *(const uint2*)(g_heattr_h + (size_t)g_nidx[j + k] * 64 + lane * 2);
            acc[k].x += __uint_as_float(u.x << 16);
            acc[k].y += __uint_as_float(u.x & 0xffff0000u);
            acc[k].z += __uint_as_float(u.y << 16);
            acc[k].w += __uint_as_float(u.y & 0xffff0000u);
        }
    }
    for (; j < end; j++) {
        uint2 u = *(const uint2*)(g_heattr_h + (size_t)g_nidx[j] * 64 + lane * 2);
        acc[0].x += __uint_as_float(u.x << 16);
        acc[0].y += __uint_as_float(u.x & 0xffff0000u);
        acc[0].z += __uint_as_float(u.y << 16);
        acc[0].w += __uint_as_float(u.y & 0xffff0000u);
    }

    float s = 1.0f / ((float)(end - beg) + EPS);
    float4 xn = ((const float4*)g_xnode)[(size_t)w * 32 + lane];
    float4 b  = ((const float4*)bias)[lane];
    float4 o;
    o.x = ((acc[0].x + acc[1].x) + (acc[2].x + acc[3].x)) * s + xn.x + b.x;
    o.y = ((acc[0].y + acc[1].y) + (acc[2].y + acc[3].y)) * s + xn.y + b.y;
    o.z = ((acc[0].z + acc[1].z) + (acc[2].z + acc[3].z)) * s + xn.z + b.z;
    o.w = ((acc[0].w + acc[1].w) + (acc[2].w + acc[3].w)) * s + xn.w + b.w;
    ((float4*)out)[(size_t)w * 32 + lane] = o;
}

// ---------------- launch -----------------------------------------------------
extern "C" void kernel_launch(void* const* d_in, const int* in_sizes, int n_in,
                              void* d_out, int out_size) {
    const float* x    = (const float*)d_in[0];
    const void*  hidx = d_in[1];
    const float* W    = (const float*)d_in[2];
    const float* bias = (const float*)d_in[3];
    float* out = (float*)d_out;

    int N   = in_sizes[0] / D;
    int nnz = in_sizes[1] / 2;

    static cudaStream_t s2 = 0;
    static cudaEvent_t evA = 0, evB = 0;
    if (!s2) {
        cudaStreamCreateWithFlags(&s2, cudaStreamNonBlocking);
        cudaEventCreateWithFlags(&evA, cudaEventDisableTiming);
        cudaEventCreateWithFlags(&evB, cudaEventDisableTiming);
        cudaFuncSetAttribute(gemm_kernel,
                             cudaFuncAttributeMaxDynamicSharedMemorySize, GEMM_SMEM);
    }

    // fork: GEMM (+bf16 mirror) runs concurrently with CSR build
    cudaEventRecord(evA, 0);
    cudaStreamWaitEvent(s2, evA, 0);
    gemm_kernel<<<(N + 63) / 64, 256, GEMM_SMEM, s2>>>(x, W, N);

    // CSR chain on capture stream
    zero_cnts_kernel<<<(E_CAP + N_CAP) / 4 / 256, 256>>>((const int*)hidx);
    int q = (nnz + 3) / 4;
    hist_kernel<<<(q + 255) / 256, 256>>>(hidx, nnz);
    scan_local_kernel<<<NBLK_SCAN, 1024>>>();
    scan_fixup_kernel<<<NBLK_SCAN, 1024>>>();
    fill_kernel<<<(q + 255) / 256, 256>>>(hidx, nnz);

    // join
    cudaEventRecord(evB, s2);
    cudaStreamWaitEvent(0, evB, 0);

    edge_agg_kernel<<<E_CAP / 2, 128>>>();
    node_agg_kernel<<<(N + 7) / 8, 256>>>(bias, out, N);
}

// round 5
// speedup vs baseline: 1.4387x; 1.4387x over previous
#include <cuda_runtime.h>
#include <cuda_bf16.h>
#include <stdint.h>

#define D 128
#define E_CAP 16384
#define N_CAP 65536
#define NNZ_CAP (1 << 20)
#define EPS 1e-8f
#define CHUNK 4096
#define NBLK_E (E_CAP / CHUNK)            // 4
#define NBLK_N (N_CAP / CHUNK)            // 16
#define NBLK_SCAN (NBLK_E + NBLK_N)       // 20

// ---------------- scratch (static device globals; no allocation) ------------
__device__ float    g_xnode[(size_t)N_CAP * D];      // fp32 (exact residual)
__device__ unsigned g_xnode_h[(size_t)N_CAP * 64];   // bf16x2 gather mirror
__device__ unsigned g_heattr_h[(size_t)E_CAP * 64];  // bf16x2 hyperedge attr
__device__ int g_eidx[NNZ_CAP];
__device__ int g_nidx[NNZ_CAP];
__device__ int g_eoff[E_CAP + 1];
__device__ int g_noff[N_CAP + 1];
__device__ int g_cnts[E_CAP + N_CAP];                // counts, then reused as cursors
__device__ int g_bsum[NBLK_SCAN];
__device__ int g_is64;

#define ECNT (g_cnts)
#define NCNT (g_cnts + E_CAP)

// ---------------- zero counters + index dtype detect -------------------------
__global__ void zero_cnts_kernel(const int* __restrict__ h) {
    int i = blockIdx.x * blockDim.x + threadIdx.x;
    ((int4*)g_cnts)[i] = make_int4(0, 0, 0, 0);
    if (i == 0)
        g_is64 = (h[1] == 0 && h[3] == 0 && h[5] == 0 && h[7] == 0) ? 1 : 0;
}

// ---------------- CSR build: histogram (4 entries / thread) ------------------
__global__ __launch_bounds__(256) void hist_kernel(const void* __restrict__ base, int nnz) {
    int i0 = (blockIdx.x * blockDim.x + threadIdx.x) * 4;
    if (i0 >= nnz) return;
    int m = nnz - i0; if (m > 4) m = 4;
    int src[4], e[4];
    if (g_is64) {
        const long long* p = (const long long*)base;
        #pragma unroll
        for (int k = 0; k < 4; k++) {
            int i = i0 + ((k < m) ? k : 0);
            src[k] = (int)__ldg(p + i);
            e[k]   = (int)__ldg(p + nnz + i);
        }
    } else {
        const int* p = (const int*)base;
        #pragma unroll
        for (int k = 0; k < 4; k++) {
            int i = i0 + ((k < m) ? k : 0);
            src[k] = __ldg(p + i);
            e[k]   = __ldg(p + nnz + i);
        }
    }
    #pragma unroll
    for (int k = 0; k < 4; k++) {
        if (k < m) {
            atomicAdd(&ECNT[e[k]], 1);
            atomicAdd(&NCNT[src[k]], 1);
        }
    }
}

// ---------------- CSR build: 2-level exclusive scan --------------------------
__global__ __launch_bounds__(1024) void scan_local_kernel() {
    int b = blockIdx.x;
    const int* cnt; int* off; int lo;
    if (b < NBLK_E) { cnt = ECNT; off = g_eoff; lo = b * CHUNK; }
    else            { cnt = NCNT; off = g_noff; lo = (b - NBLK_E) * CHUNK; }

    __shared__ int wsum[32];
    int tid = threadIdx.x, lane = tid & 31, wid = tid >> 5;
    int idx = lo + tid * 4;

    int4 v = *(const int4*)(cnt + idx);
    int tsum = v.x + v.y + v.z + v.w;
    int incl = tsum;
    #pragma unroll
    for (int s = 1; s < 32; s <<= 1) {
        int t = __shfl_up_sync(0xffffffffu, incl, s);
        if (lane >= s) incl += t;
    }
    if (lane == 31) wsum[wid] = incl;
    __syncthreads();
    if (wid == 0) {
        int w = wsum[lane];
        int wi = w;
        #pragma unroll
        for (int s = 1; s < 32; s <<= 1) {
            int t = __shfl_up_sync(0xffffffffu, wi, s);
            if (lane >= s) wi += t;
        }
        wsum[lane] = wi - w;
    }
    __syncthreads();
    int ex = wsum[wid] + incl - tsum;
    off[idx]     = ex;
    off[idx + 1] = ex + v.x;
    off[idx + 2] = ex + v.x + v.y;
    off[idx + 3] = ex + v.x + v.y + v.z;
    if (tid == 1023) g_bsum[b] = ex + tsum;
}

// fixup adds cross-block base AND initializes cursors (= start offsets)
__global__ __launch_bounds__(1024) void scan_fixup_kernel() {
    int b = blockIdx.x;
    __shared__ int s_base;
    int tid = threadIdx.x;
    if (tid == 0) {
        int start = (b < NBLK_E) ? 0 : NBLK_E;
        int base = 0;
        for (int i = start; i < b; i++) base += g_bsum[i];
        s_base = base;
    }
    __syncthreads();
    int base = s_base;
    int* off; int* cur; int lo;
    if (b < NBLK_E) { off = g_eoff; cur = ECNT; lo = b * CHUNK; }
    else            { off = g_noff; cur = NCNT; lo = (b - NBLK_E) * CHUNK; }
    int idx = lo + tid * 4;
    int4 o = *(int4*)(off + idx);
    o.x += base; o.y += base; o.z += base; o.w += base;
    *(int4*)(off + idx) = o;
    *(int4*)(cur + idx) = o;   // cursors start at segment start
    if (tid == 0) {
        if (b == NBLK_E - 1)    g_eoff[E_CAP] = base + g_bsum[b];
        if (b == NBLK_SCAN - 1) g_noff[N_CAP] = base + g_bsum[b];
    }
}

// ---------------- CSR build: bucket fill (cursor atomics, 4/thread) ----------
__global__ __launch_bounds__(256) void fill_kernel(const void* __restrict__ base, int nnz) {
    int i0 = (blockIdx.x * blockDim.x + threadIdx.x) * 4;
    if (i0 >= nnz) return;
    int m = nnz - i0; if (m > 4) m = 4;
    int src[4], e[4];
    if (g_is64) {
        const long long* p = (const long long*)base;
        #pragma unroll
        for (int k = 0; k < 4; k++) {
            int i = i0 + ((k < m) ? k : 0);
            src[k] = (int)__ldg(p + i);
            e[k]   = (int)__ldg(p + nnz + i);
        }
    } else {
        const int* p = (const int*)base;
        #pragma unroll
        for (int k = 0; k < 4; k++) {
            int i = i0 + ((k < m) ? k : 0);
            src[k] = __ldg(p + i);
            e[k]   = __ldg(p + nnz + i);
        }
    }
    #pragma unroll
    for (int k = 0; k < 4; k++) {
        if (k < m) {
            int pe = atomicAdd(&ECNT[e[k]], 1);
            g_eidx[pe] = src[k];
            int pn = atomicAdd(&NCNT[src[k]], 1);
            g_nidx[pn] = e[k];
        }
    }
}

// ---------------- GEMM: g_xnode = x @ W^T (packed f32x2 FMA) -----------------
#define WT_STRIDE 132
#define GEMM_SMEM ((128 * WT_STRIDE + 64 * WT_STRIDE) * 4)

__device__ __forceinline__ unsigned long long fma2(unsigned long long a,
                                                   unsigned long long b,
                                                   unsigned long long c) {
    unsigned long long d;
    asm("fma.rn.f32x2 %0, %1, %2, %3;" : "=l"(d) : "l"(a), "l"(b), "l"(c));
    return d;
}

__global__ __launch_bounds__(256) void gemm_kernel(const float* __restrict__ x,
                                                   const float* __restrict__ W,
                                                   int N) {
    extern __shared__ float sm[];
    float* WT = sm;                       // [128][132], WT[k][j] = W[j][k]
    float* Xs = sm + 128 * WT_STRIDE;     // [64][132]

    int t = threadIdx.x;
    int row0 = blockIdx.x * 64;

    #pragma unroll
    for (int i = 0; i < 64; i++) {
        int idx = t + i * 256;
        int j = idx >> 7, k = idx & 127;
        WT[k * WT_STRIDE + j] = W[idx];
    }
    #pragma unroll
    for (int i = 0; i < 32; i++) {
        int idx = t + i * 256;
        int r = idx >> 7, k = idx & 127;
        int row = row0 + r;
        if (row >= N) row = N - 1;
        Xs[r * WT_STRIDE + k] = x[(size_t)row * D + k];
    }
    __syncthreads();

    int tx = t & 15, ty = t >> 4;
    int c0 = tx * 8, r0 = ty * 4;

    unsigned long long acc[4][4];
    #pragma unroll
    for (int i = 0; i < 4; i++)
        #pragma unroll
        for (int j = 0; j < 4; j++) acc[i][j] = 0ull;

    #pragma unroll 4
    for (int k = 0; k < 128; k++) {
        ulonglong2 wa = *(const ulonglong2*)(WT + k * WT_STRIDE + c0);
        ulonglong2 wb = *(const ulonglong2*)(WT + k * WT_STRIDE + c0 + 4);
        #pragma unroll
        for (int i = 0; i < 4; i++) {
            unsigned au = __float_as_uint(Xs[(r0 + i) * WT_STRIDE + k]);
            unsigned long long aa;
            asm("mov.b64 %0, {%1, %1};" : "=l"(aa) : "r"(au));
            acc[i][0] = fma2(aa, wa.x, acc[i][0]);
            acc[i][1] = fma2(aa, wa.y, acc[i][1]);
            acc[i][2] = fma2(aa, wb.x, acc[i][2]);
            acc[i][3] = fma2(aa, wb.y, acc[i][3]);
        }
    }

    #pragma unroll
    for (int i = 0; i < 4; i++) {
        int row = row0 + r0 + i;
        if (row < N) {
            ulonglong2 o0; o0.x = acc[i][0]; o0.y = acc[i][1];
            ulonglong2 o1; o1.x = acc[i][2]; o1.y = acc[i][3];
            *(ulonglong2*)(g_xnode + (size_t)row * D + c0)     = o0;
            *(ulonglong2*)(g_xnode + (size_t)row * D + c0 + 4) = o1;
            uint4 h;
            #pragma unroll
            for (int j = 0; j < 4; j++) {
                unsigned lo, hi;
                asm("mov.b64 {%0, %1}, %2;" : "=r"(lo), "=r"(hi) : "l"(acc[i][j]));
                unsigned r2;
                asm("cvt.rn.bf16x2.f32 %0, %1, %2;" : "=r"(r2)
                    : "f"(__uint_as_float(hi)), "f"(__uint_as_float(lo)));
                ((unsigned*)&h)[j] = r2;
            }
            *(uint4*)(g_xnode_h + (size_t)row * 64 + tx * 4) = h;
        }
    }
}

// ---------------- phase A: per-edge pull reduction (R3 form, unroll 2) -------
__global__ __launch_bounds__(128) void edge_agg_kernel() {
    int half = threadIdx.x >> 6;
    int t = threadIdx.x & 63;
    int e = blockIdx.x * 2 + half;
    int beg = g_eoff[e], end = g_eoff[e + 1];
    if (beg == end) return;

    float s0a = 0.f, s1a = 0.f, s0b = 0.f, s1b = 0.f;
    int j = beg;
    for (; j + 2 <= end; j += 2) {
        int n0 = g_eidx[j], n1 = g_eidx[j + 1];
        unsigned u0 = g_xnode_h[(size_t)n0 * 64 + t];
        unsigned u1 = g_xnode_h[(size_t)n1 * 64 + t];
        s0a += __uint_as_float(u0 << 16);
        s1a += __uint_as_float(u0 & 0xffff0000u);
        s0b += __uint_as_float(u1 << 16);
        s1b += __uint_as_float(u1 & 0xffff0000u);
    }
    if (j < end) {
        unsigned u = g_xnode_h[(size_t)g_eidx[j] * 64 + t];
        s0a += __uint_as_float(u << 16);
        s1a += __uint_as_float(u & 0xffff0000u);
    }
    float inv = 1.0f / ((float)(end - beg) + EPS);
    float f0 = (s0a + s0b) * inv;
    float f1 = (s1a + s1b) * inv;
    unsigned r;
    asm("cvt.rn.bf16x2.f32 %0, %1, %2;" : "=r"(r) : "f"(f1), "f"(f0));
    g_heattr_h[(size_t)e * 64 + t] = r;
}

// ---------------- phase B: per-node pull + fused finalize (R3 form) ----------
__global__ __launch_bounds__(256) void node_agg_kernel(const float* __restrict__ bias,
                                                       float* __restrict__ out,
                                                       int N) {
    int w = (blockIdx.x * blockDim.x + threadIdx.x) >> 5;
    if (w >= N) return;
    int lane = threadIdx.x & 31;
    int beg = g_noff[w], end = g_noff[w + 1];

    float4 a = make_float4(0.f, 0.f, 0.f, 0.f);
    float4 a2 = make_float4(0.f, 0.f, 0.f, 0.f);
    int j = beg;
    for (; j + 2 <= end; j += 2) {
        int e0 = g_nidx[j], e1 = g_nidx[j + 1];
        uint2 u0 = *(const uint2*)(g_heattr_h + (size_t)e0 * 64 + lane * 2);
        uint2 u1 = *(const uint2*)(g_heattr_h + (size_t)e1 * 64 + lane * 2);
        a.x  += __uint_as_float(u0.x << 16);
        a.y  += __uint_as_float(u0.x & 0xffff0000u);
        a.z  += __uint_as_float(u0.y << 16);
        a.w  += __uint_as_float(u0.y & 0xffff0000u);
        a2.x += __uint_as_float(u1.x << 16);
        a2.y += __uint_as_float(u1.x & 0xffff0000u);
        a2.z += __uint_as_float(u1.y << 16);
        a2.w += __uint_as_float(u1.y & 0xffff0000u);
    }
    if (j < end) {
        uint2 u = *(const uint2*)(g_heattr_h + (size_t)g_nidx[j] * 64 + lane * 2);
        a.x += __uint_as_float(u.x << 16);
        a.y += __uint_as_float(u.x & 0xffff0000u);
        a.z += __uint_as_float(u.y << 16);
        a.w += __uint_as_float(u.y & 0xffff0000u);
    }

    float s = 1.0f / ((float)(end - beg) + EPS);
    float4 xn = ((const float4*)g_xnode)[(size_t)w * 32 + lane];
    float4 b  = ((const float4*)bias)[lane];
    float4 o;
    o.x = (a.x + a2.x) * s + xn.x + b.x;
    o.y = (a.y + a2.y) * s + xn.y + b.y;
    o.z = (a.z + a2.z) * s + xn.z + b.z;
    o.w = (a.w + a2.w) * s + xn.w + b.w;
    ((float4*)out)[(size_t)w * 32 + lane] = o;
}

// ---------------- launch -----------------------------------------------------
extern "C" void kernel_launch(void* const* d_in, const int* in_sizes, int n_in,
                              void* d_out, int out_size) {
    const float* x    = (const float*)d_in[0];
    const void*  hidx = d_in[1];
    const float* W    = (const float*)d_in[2];
    const float* bias = (const float*)d_in[3];
    float* out = (float*)d_out;

    int N   = in_sizes[0] / D;
    int nnz = in_sizes[1] / 2;

    static cudaStream_t s2 = 0;
    static cudaEvent_t evA = 0, evB = 0;
    if (!s2) {
        cudaStreamCreateWithFlags(&s2, cudaStreamNonBlocking);
        cudaEventCreateWithFlags(&evA, cudaEventDisableTiming);
        cudaEventCreateWithFlags(&evB, cudaEventDisableTiming);
        cudaFuncSetAttribute(gemm_kernel,
                             cudaFuncAttributeMaxDynamicSharedMemorySize, GEMM_SMEM);
    }

    // fork: GEMM (+bf16 mirror) runs concurrently with CSR build
    cudaEventRecord(evA, 0);
    cudaStreamWaitEvent(s2, evA, 0);
    gemm_kernel<<<(N + 63) / 64, 256, GEMM_SMEM, s2>>>(x, W, N);

    // CSR chain on capture stream
    zero_cnts_kernel<<<(E_CAP + N_CAP) / 4 / 256, 256>>>((const int*)hidx);
    int q = (nnz + 3) / 4;
    hist_kernel<<<(q + 255) / 256, 256>>>(hidx, nnz);
    scan_local_kernel<<<NBLK_SCAN, 1024>>>();
    scan_fixup_kernel<<<NBLK_SCAN, 1024>>>();
    fill_kernel<<<(q + 255) / 256, 256>>>(hidx, nnz);

    // join
    cudaEventRecord(evB, s2);
    cudaStreamWaitEvent(0, evB, 0);

    edge_agg_kernel<<<E_CAP / 2, 128>>>();
    node_agg_kernel<<<(N + 7) / 8, 256>>>(bias, out, N);
}